// round 15
// baseline (speedup 1.0000x reference)
#include <cuda_runtime.h>
#include <cstdint>

#define En 4096
#define Bn 8
#define HEADS 32
#define Dh 128
#define CK 128                // k-floats per chunk
#define RB 16                 // W rows per block
#define SN 4                  // per-warp W pipeline stages
#define KS 4                  // k-splits per output row
#define KBLK (En / KS)        // 1024 k per block
#define KCH (KBLK / CK)       // 8 chunks

typedef unsigned long long u64;

// qkv partials: [ks][proj][b][4096]
__device__ __align__(16) float g_part[KS * 3 * Bn * En];
__device__ __align__(16) float g_o[Bn * En];

struct Smem {
    float x[Bn][KBLK];        // 32KB, block-resident
    float w[4][SN][4][CK];    // 32KB, [warp][stage][row][col], thread-private slices
};                            // 64KB dynamic

__device__ __forceinline__ void fma2(u64 &d, u64 a, u64 b) {
    asm("fma.rn.f32x2 %0, %1, %2, %0;" : "+l"(d) : "l"(a), "l"(b));
}
__device__ __forceinline__ float2 unpack2(u64 v) {
    float2 r; asm("mov.b64 {%0,%1}, %2;" : "=f"(r.x), "=f"(r.y) : "l"(v)); return r;
}
__device__ __forceinline__ void cp16(uint32_t saddr, const float* g) {
    asm volatile("cp.async.cg.shared.global [%0], [%1], 16;" :: "r"(saddr), "l"(g));
}
__device__ __forceinline__ void gdc_wait() {
    asm volatile("griddepcontrol.wait;" ::: "memory");
}
__device__ __forceinline__ void gdc_launch_dep() {
    asm volatile("griddepcontrol.launch_dependents;" ::: "memory");
}
#define COMMIT() asm volatile("cp.async.commit_group;")
#define WAITG(n) asm volatile("cp.async.wait_group %0;" :: "n"(n))

// butterfly transpose-reduce of 32 per-thread partials -> 1 value/lane
__device__ __forceinline__ float reduce32(u64* acc, int lane, int& r_out, int& b_out) {
    float vals[32];
#pragma unroll
    for (int i = 0; i < 32; ++i) {
        float2 p = unpack2(acc[i]);
        vals[i] = p.x + p.y;
    }
    int n = 32;
#pragma unroll
    for (int m = 1; m <= 16; m <<= 1) {
        n >>= 1;
        bool up = (lane & m) != 0;
#pragma unroll
        for (int i = 0; i < n; ++i) {
            float keep = up ? vals[i + n] : vals[i];
            float send = up ? vals[i] : vals[i + n];
            keep += __shfl_xor_sync(0xffffffffu, send, m);
            vals[i] = keep;
        }
    }
    int j = ((lane & 1) << 4) | ((lane & 2) << 2) | (lane & 4) |
            ((lane >> 2) & 2) | ((lane >> 4) & 1);
    r_out = j >> 3;
    b_out = j & 7;
    return vals[0];
}

// one W stage for this warp: lane copies EXACTLY the 4x16B it later reads
__device__ __forceinline__ void issue_wstage(uint32_t swb, const float* wbase,
                                             int slot, int kc, int lane) {
#pragma unroll
    for (int p = 0; p < 4; ++p)
        cp16(swb + (uint32_t)(slot * (4 * CK * 4) + (p * 32 + lane) * 16),
             wbase + (size_t)p * En + kc * CK + lane * 4);
}
// x tile: 2048 16B units over 128 threads (thread-sliced; one barrier publishes)
__device__ __forceinline__ void issue_x(uint32_t sxb, const float* X, int k0, int t) {
#pragma unroll
    for (int p = 0; p < 16; ++p) {
        int u = p * 128 + t;
        int b = u >> 8, col = u & 255;
        cp16(sxb + u * 16, X + (size_t)b * En + k0 + col * 4);
    }
}

__device__ __forceinline__ void consume(Smem& sm, u64* acc, int warp, int lane,
                                        int slot, int i) {
    longlong2 wv[4];
#pragma unroll
    for (int r = 0; r < 4; ++r)
        wv[r] = *reinterpret_cast<const longlong2*>(&sm.w[warp][slot][r][lane * 4]);
#pragma unroll
    for (int b = 0; b < 8; ++b) {
        longlong2 xv = *reinterpret_cast<const longlong2*>(&sm.x[b][i * CK + lane * 4]);
#pragma unroll
        for (int r = 0; r < 4; ++r) {
            fma2(acc[r * 8 + b], (u64)wv[r].x, (u64)xv.x);
            fma2(acc[r * 8 + b], (u64)wv[r].y, (u64)xv.y);
        }
    }
}

// barrier-free mainloop, shared by qkv/oproj (prologues differ)
__device__ __forceinline__ void mainloop(Smem& sm, u64* acc, uint32_t swb,
                                         const float* wbase, int warp, int lane) {
    for (int i = 0; i < KCH; ++i) {
        if (i < KCH - 2) WAITG(2);
        else if (i == KCH - 2) WAITG(1);
        else WAITG(0);
        int nk = i + SN - 1;
        if (nk < KCH) { issue_wstage(swb, wbase, nk & (SN - 1), nk, lane); COMMIT(); }
        consume(sm, acc, warp, lane, i & (SN - 1), i);
    }
}

// ---------- qkv ----------
__global__ void __launch_bounds__(128, 3)
qkv_kernel(const float* __restrict__ Wq, const float* __restrict__ Wk,
           const float* __restrict__ Wv, const float* __restrict__ x) {
    gdc_launch_dep();
    extern __shared__ char smraw[];
    Smem& sm = *reinterpret_cast<Smem*>(smraw);
    const int t = threadIdx.x, warp = t >> 5, lane = t & 31;
    int rb = blockIdx.x >> 2, ks = blockIdx.x & 3;
    int row0 = rb * RB, k0 = ks * KBLK;
    const float* W = (blockIdx.y == 0) ? Wq : ((blockIdx.y == 1) ? Wk : Wv);
    float* out = g_part + (size_t)(ks * 3 + blockIdx.y) * Bn * En;

    uint32_t sxb = (uint32_t)__cvta_generic_to_shared(&sm.x[0][0]);
    uint32_t swb = (uint32_t)__cvta_generic_to_shared(&sm.w[warp][0][0][0]);
    const float* wbase = W + (size_t)(row0 + warp * 4) * En + k0;

    // groups: [X, W0, W1, W2]; stage s ready after group s+1
    issue_x(sxb, x, k0, t); COMMIT();
#pragma unroll
    for (int s = 0; s < SN - 1; ++s) { issue_wstage(swb, wbase, s, s, lane); COMMIT(); }
    WAITG(2);          // own X + W0 complete
    __syncthreads();   // everyone's X slices complete -> x visible

    u64 acc[32];
#pragma unroll
    for (int i = 0; i < 32; ++i) acc[i] = 0ull;

    mainloop(sm, acc, swb, wbase, warp, lane);

    int r, b;
    float v = reduce32(acc, lane, r, b);
    out[(size_t)b * En + row0 + warp * 4 + r] = v;
}

// ---------- attn: PDL; zeroes d_out pre-wait; sums partials ----------
__global__ void __launch_bounds__(256)
attn_kernel(float* __restrict__ out) {
    gdc_launch_dep();
    int gtid = blockIdx.x * blockDim.x + threadIdx.x;
    reinterpret_cast<float4*>(out)[gtid] = make_float4(0.f, 0.f, 0.f, 0.f);

    gdc_wait();  // all qkv partials written

    int warp = gtid >> 5;
    int lane = gtid & 31;
    int b = warp >> 5;
    int h = warp & 31;

    float4 qv = make_float4(0.f, 0.f, 0.f, 0.f);
    float4 kv = qv, vv = qv;
#pragma unroll
    for (int ksp = 0; ksp < KS; ++ksp) {
        size_t base = (size_t)(ksp * 3) * Bn * En + (size_t)b * En + h * Dh + lane * 4;
        float4 a0 = *reinterpret_cast<const float4*>(g_part + base);
        float4 a1 = *reinterpret_cast<const float4*>(g_part + base + (size_t)Bn * En);
        float4 a2 = *reinterpret_cast<const float4*>(g_part + base + (size_t)2 * Bn * En);
        qv.x += a0.x; qv.y += a0.y; qv.z += a0.z; qv.w += a0.w;
        kv.x += a1.x; kv.y += a1.y; kv.z += a1.z; kv.w += a1.w;
        vv.x += a2.x; vv.y += a2.y; vv.z += a2.z; vv.w += a2.w;
    }

    float sq = qv.x + qv.y + qv.z + qv.w;
    float dp = qv.x * kv.x + qv.y * kv.y + qv.z * kv.z + qv.w * kv.w;
#pragma unroll
    for (int m = 16; m >= 1; m >>= 1) {
        sq += __shfl_xor_sync(0xffffffffu, sq, m);
        dp += __shfl_xor_sync(0xffffffffu, dp, m);
    }

    const float scale = 0.08838834764831845f;  // 1/sqrt(128)
    float s0 = sq * scale;
    float sL = dp * scale;
    float mx = fmaxf(s0, sL);
    float e0 = expf(s0 - mx);
    float eL = expf(sL - mx);
    float inv = 1.0f / (4095.0f * e0 + eL);
    float c1 = 4095.0f * e0 * inv;
    float c2 = eL * inv;

    float4* o4 = reinterpret_cast<float4*>(g_o + b * En + h * Dh);
    o4[lane] = make_float4(c1 + c2 * vv.x, c1 + c2 * vv.y,
                           c1 + c2 * vv.z, c1 + c2 * vv.w);
}

// ---------- oproj: PDL; all Wo stages pre-wait, x post, drain once ----------
__global__ void __launch_bounds__(128, 3)
oproj_kernel(const float* __restrict__ Wo, float* __restrict__ out) {
    extern __shared__ char smraw[];
    Smem& sm = *reinterpret_cast<Smem*>(smraw);
    const int t = threadIdx.x, warp = t >> 5, lane = t & 31;
    int rb = blockIdx.x >> 2, ks = blockIdx.x & 3;
    int row0 = rb * RB, k0 = ks * KBLK;

    uint32_t sxb = (uint32_t)__cvta_generic_to_shared(&sm.x[0][0]);
    uint32_t swb = (uint32_t)__cvta_generic_to_shared(&sm.w[warp][0][0][0]);
    const float* wbase = Wo + (size_t)(row0 + warp * 4) * En + k0;

    // groups: [W0, W1, W2, X] — Wo prefetch overlaps qkv's drain
#pragma unroll
    for (int s = 0; s < SN - 1; ++s) { issue_wstage(swb, wbase, s, s, lane); COMMIT(); }

    gdc_wait();  // attn done -> g_o and zeroed out visible

    issue_x(sxb, g_o, k0, t); COMMIT();
    WAITG(0);          // drain: all own W stages + X slices complete
    __syncthreads();   // everyone's X slices complete

    u64 acc[32];
#pragma unroll
    for (int i = 0; i < 32; ++i) acc[i] = 0ull;

    mainloop(sm, acc, swb, wbase, warp, lane);

    int r, b;
    float v = reduce32(acc, lane, r, b);
    atomicAdd(&out[(size_t)b * En + row0 + warp * 4 + r], v);
}

extern "C" void kernel_launch(void* const* d_in, const int* in_sizes, int n_in,
                              void* d_out, int out_size) {
    const float* x  = (const float*)d_in[0];
    const float* Wq = (const float*)d_in[1];
    const float* Wk = (const float*)d_in[2];
    const float* Wv = (const float*)d_in[3];
    const float* Wo = (const float*)d_in[4];
    float* out = (float*)d_out;

    static int attr_set = 0;
    if (!attr_set) {
        cudaFuncSetAttribute(qkv_kernel, cudaFuncAttributeMaxDynamicSharedMemorySize,
                             (int)sizeof(Smem));
        cudaFuncSetAttribute(oproj_kernel, cudaFuncAttributeMaxDynamicSharedMemorySize,
                             (int)sizeof(Smem));
        attr_set = 1;
    }

    dim3 gq(1024, 3);
    qkv_kernel<<<gq, 128, sizeof(Smem)>>>(Wq, Wk, Wv, x);

    cudaLaunchAttribute at[1];
    at[0].id = cudaLaunchAttributeProgrammaticStreamSerialization;
    at[0].val.programmaticStreamSerializationAllowed = 1;

    cudaLaunchConfig_t cfg_attn = {};
    cfg_attn.gridDim = dim3(32);
    cfg_attn.blockDim = dim3(256);
    cfg_attn.attrs = at;
    cfg_attn.numAttrs = 1;
    cudaLaunchKernelEx(&cfg_attn, attn_kernel, out);

    cudaLaunchConfig_t cfg_opj = {};
    cfg_opj.gridDim = dim3(1024);
    cfg_opj.blockDim = dim3(128);
    cfg_opj.dynamicSmemBytes = sizeof(Smem);
    cfg_opj.attrs = at;
    cfg_opj.numAttrs = 1;
    cudaLaunchKernelEx(&cfg_opj, oproj_kernel, (const float*)Wo, out);
}